// round 10
// baseline (speedup 1.0000x reference)
#include <cuda_runtime.h>
#include <math.h>

#define BS 8
#define LQ 300
#define NQ (BS*LQ)        // 2400
#define DIM 256
#define NH 8
#define NL 4
#define NP 4
#define LEN_V 34000
#define NPOINT 128        // NH*NL*NP

__constant__ int c_lvlW[4]     = {160, 80, 40, 20};
__constant__ int c_lvlStart[4] = {0, 25600, 32000, 33600};

// Scratch
__device__ float g_P[NQ * 384];                    // [off(256) | attn(128)]
__device__ float g_agg[(size_t)NH * NQ * DIM];     // [h][q][c]
__device__ float g_wsum[NQ * NH];
__device__ float g_Y[NQ * DIM];

// ---------------------------------------------------------------------------
// Scalar-FFMA GEMM, dual weight set. Tile 16(M) x 64(N), 64 THREADS (2 warps).
// Micro-tile 4x4 (2 LDS.128 + 16 FFMA per k); 4+ small blocks per SM so
// sync/latency bubbles overlap across independent blocks.
// A rows padded to 20 floats (80 B) -> float4-aligned.
// ---------------------------------------------------------------------------
__global__ void __launch_bounds__(64) gemm_dual_kernel(
    const float* __restrict__ A, int lda,
    const float* __restrict__ W0, const float* __restrict__ b0, int nyW0,
    const float* __restrict__ W1, const float* __restrict__ b1,
    float* __restrict__ C, int ldc, int M)
{
    __shared__ __align__(16) float As[2][16][20];   // [buf][k][row(16)+pad4]
    __shared__ __align__(16) float Bs[2][16][68];   // [buf][k][col(64)+pad4]
    const int tid = threadIdx.x;      // 0..63
    const int tx = tid & 3;           // rows tx*4 .. tx*4+3
    const int ty = tid >> 2;          // cols ty*4 .. ty*4+3  (0..15)
    const int row0 = blockIdx.x * 16;
    const int ar = tid >> 2;          // 0..15 (A load row)
    const int akq = (tid & 3) * 4;    // A k offset (float4)

    const float* W; const float* bias; int col0, colOff;
    if ((int)blockIdx.y < nyW0) {
        W = W0; bias = b0; col0 = blockIdx.y * 64; colOff = 0;
    } else {
        W = W1; bias = b1; col0 = (blockIdx.y - nyW0) * 64; colOff = nyW0 * 64;
    }

    int arow = row0 + ar; if (arow >= M) arow = M - 1;
    const float* aptr = A + (size_t)arow * lda + akq;
    const float* wptr = W + (size_t)(col0 + tid) * 256;   // thread owns col `tid`

    float acc[4][4];
#pragma unroll
    for (int i = 0; i < 4; ++i)
#pragma unroll
        for (int j = 0; j < 4; ++j) acc[i][j] = 0.f;

    float4 va = *(const float4*)(aptr);
    float4 vw[4];
#pragma unroll
    for (int q = 0; q < 4; ++q) vw[q] = *(const float4*)(wptr + q * 4);

    int buf = 0;
    for (int kc = 0; kc < 256; kc += 16) {
        As[buf][akq + 0][ar] = va.x; As[buf][akq + 1][ar] = va.y;
        As[buf][akq + 2][ar] = va.z; As[buf][akq + 3][ar] = va.w;
#pragma unroll
        for (int q = 0; q < 4; ++q) {
            Bs[buf][q * 4 + 0][tid] = vw[q].x;
            Bs[buf][q * 4 + 1][tid] = vw[q].y;
            Bs[buf][q * 4 + 2][tid] = vw[q].z;
            Bs[buf][q * 4 + 3][tid] = vw[q].w;
        }
        __syncthreads();
        if (kc + 16 < 256) {
            va = *(const float4*)(aptr + kc + 16);
#pragma unroll
            for (int q = 0; q < 4; ++q)
                vw[q] = *(const float4*)(wptr + kc + 16 + q * 4);
        }
#pragma unroll
        for (int k = 0; k < 16; ++k) {
            float4 a4 = *(const float4*)&As[buf][k][tx * 4];
            float4 b4 = *(const float4*)&Bs[buf][k][ty * 4];
            float a[4] = {a4.x, a4.y, a4.z, a4.w};
            float b[4] = {b4.x, b4.y, b4.z, b4.w};
#pragma unroll
            for (int i = 0; i < 4; ++i)
#pragma unroll
                for (int j = 0; j < 4; ++j)
                    acc[i][j] += a[i] * b[j];
        }
        buf ^= 1;
    }

    const int gc = col0 + ty * 4;
    float4 bv4 = make_float4(bias[gc], bias[gc + 1], bias[gc + 2], bias[gc + 3]);
#pragma unroll
    for (int i = 0; i < 4; ++i) {
        int r = row0 + tx * 4 + i;
        if (r < M) {
            float4 o = make_float4(acc[i][0] + bv4.x, acc[i][1] + bv4.y,
                                   acc[i][2] + bv4.z, acc[i][3] + bv4.w);
            *(float4*)(&C[(size_t)r * ldc + colOff + gc]) = o;
        }
    }
}

// ---------------------------------------------------------------------------
// Fused prep + gather (unchanged — proven round-5 hot path, at traffic floor).
// ---------------------------------------------------------------------------
__global__ void gather_kernel(const float* __restrict__ value,
                              const float* __restrict__ refpts)
{
    __shared__ float4 sPt4[NH * 32];
    __shared__ float  sm_aw[NPOINT];
    __shared__ float  sWsum[NH];

    const int bq = blockIdx.x;
    const int b = bq / LQ;
    const int tid = threadIdx.x;

    if (tid < NH) sWsum[tid] = 0.f;
    if (tid < NPOINT) sm_aw[tid] = g_P[bq * 384 + 256 + tid];
    __syncthreads();

    if (tid < NPOINT) {
        const int p = tid;
        const int h = p >> 4;
        const int rem = p & 15;
        const int l = rem >> 2;
        const int pt = rem & 3;

        float a = sm_aw[p];
        float mx = -1e30f;
#pragma unroll
        for (int i = 0; i < 16; ++i) mx = fmaxf(mx, sm_aw[h * 16 + i]);
        float ssum = 0.f;
#pragma unroll
        for (int i = 0; i < 16; ++i) ssum += expf(sm_aw[h * 16 + i] - mx);
        float w = expf(a - mx) / ssum;

        const int Wl = c_lvlW[l];
        const int base = c_lvlStart[l];
        const float fW = (float)Wl;
        float offx = g_P[bq * 384 + (((h * 4 + l) * 4 + pt) * 2) + 0];
        float offy = g_P[bq * 384 + (((h * 4 + l) * 4 + pt) * 2) + 1];
        float rx = refpts[(bq * NL + l) * 2 + 0];
        float ry = refpts[(bq * NL + l) * 2 + 1];
        float x = (rx + offx / fW) * fW - 0.5f;
        float y = (ry + offy / fW) * fW - 0.5f;

        const float fx = floorf(x), fy = floorf(y);
        const int x0 = (int)fx, y0 = (int)fy;
        const float wx = x - fx, wy = y - fy;
        const float bw[4] = {(1.f - wx) * (1.f - wy), wx * (1.f - wy),
                             (1.f - wx) * wy,         wx * wy};
        const int dx[4] = {0, 1, 0, 1};
        const int dy[4] = {0, 0, 1, 1};
        float wt[4]; int idx4[4];
        float tsum = 0.f;
#pragma unroll
        for (int t = 0; t < 4; ++t) {
            int xi = x0 + dx[t], yi = y0 + dy[t];
            bool valid = (xi >= 0) && (xi < Wl) && (yi >= 0) && (yi < Wl);
            wt[t] = valid ? w * bw[t] : 0.f;
            int xc = min(max(xi, 0), Wl - 1);
            int yc = min(max(yi, 0), Wl - 1);
            idx4[t] = (base + yc * Wl + xc) * 64;
            tsum += wt[t];
        }
        sPt4[h * 32 + rem * 2 + 0] =
            make_float4(wt[0], __int_as_float(idx4[0]), wt[1], __int_as_float(idx4[1]));
        sPt4[h * 32 + rem * 2 + 1] =
            make_float4(wt[2], __int_as_float(idx4[2]), wt[3], __int_as_float(idx4[3]));
        atomicAdd(&sWsum[h], tsum);
    }
    __syncthreads();

    const int s = tid >> 6;
    const int cq = tid & 63;
    const float4* vb = (const float4*)value + (size_t)b * ((size_t)LEN_V * 64) + cq;

#pragma unroll
    for (int hh = 0; hh < 2; ++hh) {
        const int h = s * 2 + hh;
        float accx = 0.f, accy = 0.f, accz = 0.f, accw = 0.f;
#pragma unroll 4
        for (int j = 0; j < 32; j += 2) {
            float4 p0 = sPt4[h * 32 + j];
            float4 p1 = sPt4[h * 32 + j + 1];
            float4 v0 = vb[__float_as_int(p0.y)];
            float4 v1 = vb[__float_as_int(p0.w)];
            float4 v2 = vb[__float_as_int(p1.y)];
            float4 v3 = vb[__float_as_int(p1.w)];
            accx += p0.x * v0.x + p0.z * v1.x + p1.x * v2.x + p1.z * v3.x;
            accy += p0.x * v0.y + p0.z * v1.y + p1.x * v2.y + p1.z * v3.y;
            accz += p0.x * v0.z + p0.z * v1.z + p1.x * v2.z + p1.z * v3.z;
            accw += p0.x * v0.w + p0.z * v1.w + p1.x * v2.w + p1.z * v3.w;
        }
        *(float4*)&g_agg[(((size_t)h * NQ) + bq) * DIM + cq * 4] =
            make_float4(accx, accy, accz, accw);
    }
    if (tid < NH) g_wsum[bq * NH + tid] = sWsum[tid];
}

// ---------------------------------------------------------------------------
// Per-head projection: tile 16(M) x 64(N), 64 threads, grid (150, 4).
// Col block hp covers heads 2hp (cols 0..31) and 2hp+1 (cols 32..63).
// A rows padded to 20 floats (80 B) per head -> float4-aligned.
// ---------------------------------------------------------------------------
__global__ void __launch_bounds__(64) headproj_kernel(
    const float* __restrict__ Wv, const float* __restrict__ bv)
{
    __shared__ __align__(16) float As[2][16][2][20];   // [buf][k][head][row+pad4]
    __shared__ __align__(16) float Bs[2][16][68];
    const int tid = threadIdx.x;      // 0..63
    const int tx = tid & 3;
    const int ty = tid >> 2;          // 0..15 ; head = ty>>3
    const int hp = blockIdx.y;
    const int row0 = blockIdx.x * 16;
    const int ar = tid >> 2;          // 0..15
    const int akq = (tid & 3) * 4;

    int arow = row0 + ar; if (arow >= NQ) arow = NQ - 1;
    const float* aptr0 = g_agg + (size_t)(2 * hp) * NQ * DIM + (size_t)arow * DIM + akq;
    const float* aptr1 = g_agg + (size_t)(2 * hp + 1) * NQ * DIM + (size_t)arow * DIM + akq;
    const float* wptr  = Wv + (size_t)(hp * 64 + tid) * 256;

    float acc[4][4];
#pragma unroll
    for (int i = 0; i < 4; ++i)
#pragma unroll
        for (int j = 0; j < 4; ++j) acc[i][j] = 0.f;

    float4 va0 = *(const float4*)(aptr0);
    float4 va1 = *(const float4*)(aptr1);
    float4 vw[4];
#pragma unroll
    for (int q = 0; q < 4; ++q) vw[q] = *(const float4*)(wptr + q * 4);

    int buf = 0;
    for (int kc = 0; kc < 256; kc += 16) {
        As[buf][akq + 0][0][ar] = va0.x; As[buf][akq + 1][0][ar] = va0.y;
        As[buf][akq + 2][0][ar] = va0.z; As[buf][akq + 3][0][ar] = va0.w;
        As[buf][akq + 0][1][ar] = va1.x; As[buf][akq + 1][1][ar] = va1.y;
        As[buf][akq + 2][1][ar] = va1.z; As[buf][akq + 3][1][ar] = va1.w;
#pragma unroll
        for (int q = 0; q < 4; ++q) {
            Bs[buf][q * 4 + 0][tid] = vw[q].x;
            Bs[buf][q * 4 + 1][tid] = vw[q].y;
            Bs[buf][q * 4 + 2][tid] = vw[q].z;
            Bs[buf][q * 4 + 3][tid] = vw[q].w;
        }
        __syncthreads();
        if (kc + 16 < 256) {
            va0 = *(const float4*)(aptr0 + kc + 16);
            va1 = *(const float4*)(aptr1 + kc + 16);
#pragma unroll
            for (int q = 0; q < 4; ++q)
                vw[q] = *(const float4*)(wptr + kc + 16 + q * 4);
        }
        const int hd = ty >> 3;
#pragma unroll
        for (int k = 0; k < 16; ++k) {
            float4 a4 = *(const float4*)&As[buf][k][hd][tx * 4];
            float4 b4 = *(const float4*)&Bs[buf][k][ty * 4];
            float a[4] = {a4.x, a4.y, a4.z, a4.w};
            float b[4] = {b4.x, b4.y, b4.z, b4.w};
#pragma unroll
            for (int i = 0; i < 4; ++i)
#pragma unroll
                for (int j = 0; j < 4; ++j)
                    acc[i][j] += a[i] * b[j];
        }
        buf ^= 1;
    }

    const int gc = hp * 64 + ty * 4;
    const int h = gc >> 5;
    float4 bv4 = make_float4(bv[gc], bv[gc + 1], bv[gc + 2], bv[gc + 3]);
#pragma unroll
    for (int i = 0; i < 4; ++i) {
        int r = row0 + tx * 4 + i;
        if (r < NQ) {
            float ws = g_wsum[r * NH + h];
            float4 o = make_float4(acc[i][0] + ws * bv4.x, acc[i][1] + ws * bv4.y,
                                   acc[i][2] + ws * bv4.z, acc[i][3] + ws * bv4.w);
            *(float4*)(&g_Y[(size_t)r * 256 + gc]) = o;
        }
    }
}

// ---------------------------------------------------------------------------
extern "C" void kernel_launch(void* const* d_in, const int* in_sizes, int n_in,
                              void* d_out, int out_size) {
    const float* query  = (const float*)d_in[0];
    const float* refpts = (const float*)d_in[1];
    const float* value  = (const float*)d_in[2];
    const float* Wv     = (const float*)d_in[3];
    const float* bv     = (const float*)d_in[4];
    const float* Woff   = (const float*)d_in[5];
    const float* boff   = (const float*)d_in[6];
    const float* Wattn  = (const float*)d_in[7];
    const float* battn  = (const float*)d_in[8];
    const float* Wout   = (const float*)d_in[9];
    const float* bout   = (const float*)d_in[10];
    float* out = (float*)d_out;

    float *pP = nullptr, *pY = nullptr;
    cudaGetSymbolAddress((void**)&pP, g_P);
    cudaGetSymbolAddress((void**)&pY, g_Y);

    const int MB = NQ / 16;   // 150

    // qproj: y 0..3 -> Woff (cols 0..255), y 4..5 -> Wattn (cols 256..383)
    gemm_dual_kernel<<<dim3(MB, 6), 64>>>(query, 256, Woff, boff, 4,
                                          Wattn, battn, pP, 384, NQ);
    // fused softmax/loc prep + weighted value gather -> g_agg [h][q][c], g_wsum
    gather_kernel<<<NQ, 256>>>(value, refpts);
    // per-head value projection on aggregates -> g_Y [2400 x 256]
    headproj_kernel<<<dim3(MB, 4), 64>>>(Wv, bv);
    // output projection -> out
    gemm_dual_kernel<<<dim3(MB, 4), 64>>>(pY, 256, Wout, bout, 4,
                                          (const float*)nullptr,
                                          (const float*)nullptr, out, 256, NQ);
}